// round 5
// baseline (speedup 1.0000x reference)
#include <cuda_runtime.h>
#include <stdint.h>
#include <stddef.h>

#define N_NODES 100000
#define N_EDGES 600000
#define NODE_IN 387
#define HID 128
#define EDGE_DIM 7
#define NPAD 388   // 387 padded for float4 smem weight loads

// ---------------- device scratch (allocation-free) ----------------
__device__ float g_aggr1[(size_t)N_NODES * NODE_IN];   // 155 MB (reused as gA/gB later)
__device__ float g_h1   [(size_t)N_NODES * HID];
__device__ float g_aggr2[(size_t)N_NODES * HID];
__device__ float g_h2   [(size_t)N_NODES * HID];
__device__ int   g_src[N_EDGES];
__device__ int   g_dst[N_EDGES];
__device__ int   g_is64;

// ---------------- edge index dtype detection ----------------
__global__ void detect_idx(const void* ei) {
    if (threadIdx.x == 0 && blockIdx.x == 0) {
        const long long* p = (const long long*)ei;
        int ok = 1;
        for (int i = 0; i < 1024; i++) {
            long long v = p[i];
            if (v < 0 || v >= (long long)N_NODES) { ok = 0; break; }
        }
        g_is64 = ok;
    }
}

__global__ void convert_idx(const void* ei) {
    int is64 = g_is64;
    int stride = gridDim.x * blockDim.x;
    for (int i = blockIdx.x * blockDim.x + threadIdx.x; i < 2 * N_EDGES; i += stride) {
        int v;
        if (is64) v = (int)((const long long*)ei)[i];
        else      v = ((const int*)ei)[i];
        if (i < N_EDGES) g_src[i] = v;
        else             g_dst[i - N_EDGES] = v;
    }
}

// ---------------- vectorized copy ----------------
__global__ void copy4(const float* __restrict__ src, float* __restrict__ dst, int n4) {
    int stride = gridDim.x * blockDim.x;
    const float4* s = (const float4*)src;
    float4* d = (float4*)dst;
    for (int i = blockIdx.x * blockDim.x + threadIdx.x; i < n4; i += stride)
        d[i] = s[i];
}

// ---------------- conv1 message+scatter: full 387, float4 smem weights ----------------
__global__ __launch_bounds__(256) void edge_msg387(
    const float* __restrict__ xin, const float* __restrict__ eattr,
    const float* __restrict__ wg, const float* __restrict__ bg,
    float* __restrict__ aggr)
{
    __shared__ __align__(16) float sw[EDGE_DIM * NPAD];
    __shared__ __align__(16) float sb[NPAD];
    for (int i = threadIdx.x; i < EDGE_DIM * NPAD; i += 256) {
        int c = i / NPAD, j = i % NPAD;
        sw[i] = (j < NODE_IN) ? wg[c * NODE_IN + j] : 0.f;
    }
    for (int i = threadIdx.x; i < NPAD; i += 256)
        sb[i] = (i < NODE_IN) ? bg[i] : 0.f;
    __syncthreads();

    int lane = threadIdx.x & 31;
    int gw = (blockIdx.x * 256 + threadIdx.x) >> 5;
    int nw = (gridDim.x * 256) >> 5;
    const float4* sw4 = (const float4*)sw;
    const float4* sb4 = (const float4*)sb;

    for (int p = gw; p < N_EDGES / 2; p += nw) {
        int e0 = 2 * p, e1 = e0 + 1;
        int s0 = g_src[e0], d0 = g_dst[e0];
        int s1 = g_src[e1], d1 = g_dst[e1];
        float av = (lane < 14) ? eattr[(size_t)e0 * EDGE_DIM + lane] : 0.f;
        float a0[7], a1[7];
        #pragma unroll
        for (int c = 0; c < 7; c++) {
            a0[c] = __shfl_sync(0xffffffffu, av, c);
            a1[c] = __shfl_sync(0xffffffffu, av, c + 7);
        }

        const float* xs0 = xin + (size_t)s0 * NODE_IN;
        const float* xs1 = xin + (size_t)s1 * NODE_IN;
        float* ag0 = aggr + (size_t)d0 * NODE_IN;
        float* ag1 = aggr + (size_t)d1 * NODE_IN;

        #pragma unroll
        for (int k = 0; k < 3; k++) {
            int j0 = k * 128 + 4 * lane;
            int q = j0 >> 2;
            float4 W[7];
            #pragma unroll
            for (int c = 0; c < 7; c++) W[c] = sw4[c * (NPAD / 4) + q];
            float4 B = sb4[q];

            // edge 0
            float m00 = B.x + __ldg(&xs0[j0 + 0]);
            float m01 = B.y + __ldg(&xs0[j0 + 1]);
            float m02 = B.z + __ldg(&xs0[j0 + 2]);
            float m03 = B.w + __ldg(&xs0[j0 + 3]);
            // edge 1
            float m10 = B.x + __ldg(&xs1[j0 + 0]);
            float m11 = B.y + __ldg(&xs1[j0 + 1]);
            float m12 = B.z + __ldg(&xs1[j0 + 2]);
            float m13 = B.w + __ldg(&xs1[j0 + 3]);
            #pragma unroll
            for (int c = 0; c < 7; c++) {
                m00 = fmaf(a0[c], W[c].x, m00); m10 = fmaf(a1[c], W[c].x, m10);
                m01 = fmaf(a0[c], W[c].y, m01); m11 = fmaf(a1[c], W[c].y, m11);
                m02 = fmaf(a0[c], W[c].z, m02); m12 = fmaf(a1[c], W[c].z, m12);
                m03 = fmaf(a0[c], W[c].w, m03); m13 = fmaf(a1[c], W[c].w, m13);
            }
            atomicAdd(&ag0[j0 + 0], fmaxf(m00, 0.f));
            atomicAdd(&ag0[j0 + 1], fmaxf(m01, 0.f));
            atomicAdd(&ag0[j0 + 2], fmaxf(m02, 0.f));
            atomicAdd(&ag0[j0 + 3], fmaxf(m03, 0.f));
            atomicAdd(&ag1[j0 + 0], fmaxf(m10, 0.f));
            atomicAdd(&ag1[j0 + 1], fmaxf(m11, 0.f));
            atomicAdd(&ag1[j0 + 2], fmaxf(m12, 0.f));
            atomicAdd(&ag1[j0 + 3], fmaxf(m13, 0.f));
        }
        // remainder features 384..386
        if (lane < 3) {
            int j = 384 + lane;
            float bv = sb[j];
            float m0 = bv + __ldg(&xs0[j]);
            float m1 = bv + __ldg(&xs1[j]);
            #pragma unroll
            for (int c = 0; c < 7; c++) {
                float wv = sw[c * NPAD + j];
                m0 = fmaf(a0[c], wv, m0);
                m1 = fmaf(a1[c], wv, m1);
            }
            atomicAdd(&ag0[j], fmaxf(m0, 0.f));
            atomicAdd(&ag1[j], fmaxf(m1, 0.f));
        }
    }
}

// ---------------- conv2 message+scatter (D=128, fully vectorized) ----------------
__global__ __launch_bounds__(256) void edge_msg128(
    const float* __restrict__ xin, const float* __restrict__ eattr,
    const float* __restrict__ wg, const float* __restrict__ bg,
    float* __restrict__ aggr)
{
    __shared__ __align__(16) float sw[EDGE_DIM * HID];
    __shared__ __align__(16) float sb[HID];
    for (int i = threadIdx.x; i < EDGE_DIM * HID; i += 256) sw[i] = wg[i];
    if (threadIdx.x < HID) sb[threadIdx.x] = bg[threadIdx.x];
    __syncthreads();

    int lane = threadIdx.x & 31;
    int gw = (blockIdx.x * 256 + threadIdx.x) >> 5;
    int nw = (gridDim.x * 256) >> 5;
    const float4* sw4 = (const float4*)sw;
    const float4* sb4 = (const float4*)sb;

    for (int p = gw; p < N_EDGES / 2; p += nw) {
        int e0 = 2 * p, e1 = e0 + 1;
        int s0 = g_src[e0], d0 = g_dst[e0];
        int s1 = g_src[e1], d1 = g_dst[e1];
        float av = (lane < 14) ? eattr[(size_t)e0 * EDGE_DIM + lane] : 0.f;
        float a0[7], a1[7];
        #pragma unroll
        for (int c = 0; c < 7; c++) {
            a0[c] = __shfl_sync(0xffffffffu, av, c);
            a1[c] = __shfl_sync(0xffffffffu, av, c + 7);
        }

        float4 W[7];
        #pragma unroll
        for (int c = 0; c < 7; c++) W[c] = sw4[c * 32 + lane];
        float4 B = sb4[lane];

        float4 v0 = __ldg((const float4*)(xin + (size_t)s0 * HID) + lane);
        float4 v1 = __ldg((const float4*)(xin + (size_t)s1 * HID) + lane);
        float* ag0 = aggr + (size_t)d0 * HID + 4 * lane;
        float* ag1 = aggr + (size_t)d1 * HID + 4 * lane;

        float m00 = B.x + v0.x, m01 = B.y + v0.y, m02 = B.z + v0.z, m03 = B.w + v0.w;
        float m10 = B.x + v1.x, m11 = B.y + v1.y, m12 = B.z + v1.z, m13 = B.w + v1.w;
        #pragma unroll
        for (int c = 0; c < 7; c++) {
            m00 = fmaf(a0[c], W[c].x, m00); m10 = fmaf(a1[c], W[c].x, m10);
            m01 = fmaf(a0[c], W[c].y, m01); m11 = fmaf(a1[c], W[c].y, m11);
            m02 = fmaf(a0[c], W[c].z, m02); m12 = fmaf(a1[c], W[c].z, m12);
            m03 = fmaf(a0[c], W[c].w, m03); m13 = fmaf(a1[c], W[c].w, m13);
        }
        atomicAdd(&ag0[0], fmaxf(m00, 0.f));
        atomicAdd(&ag0[1], fmaxf(m01, 0.f));
        atomicAdd(&ag0[2], fmaxf(m02, 0.f));
        atomicAdd(&ag0[3], fmaxf(m03, 0.f));
        atomicAdd(&ag1[0], fmaxf(m10, 0.f));
        atomicAdd(&ag1[1], fmaxf(m11, 0.f));
        atomicAdd(&ag1[2], fmaxf(m12, 0.f));
        atomicAdd(&ag1[3], fmaxf(m13, 0.f));
    }
}

// ---------------- tf32 helpers ----------------
__device__ __forceinline__ uint32_t f2tf32(float f) {
    uint32_t u;
    asm("cvt.rna.tf32.f32 %0, %1;" : "=r"(u) : "f"(f));
    return u;
}

// ---------------- standalone tf32 GEMM (for gA/gB): C = A[M,K]@W[K,128] ----------------
template<bool RELU, bool BIAS>
__global__ __launch_bounds__(256) void gemm_tc(
    const float* __restrict__ A, const float* __restrict__ W,
    const float* __restrict__ bias, float* __restrict__ C,
    int M, int K)
{
    __shared__ uint32_t As[128][36];
    __shared__ uint32_t Bs[32][132];

    int t = threadIdx.x;
    int lane = t & 31;
    int warp = t >> 5;
    int wm = warp & 3;
    int wn = warp >> 2;
    int row0 = blockIdx.x * 128;
    bool k4 = (K & 3) == 0;

    float c[2][8][4];
    #pragma unroll
    for (int mt = 0; mt < 2; mt++)
        #pragma unroll
        for (int nt = 0; nt < 8; nt++)
            #pragma unroll
            for (int i = 0; i < 4; i++) c[mt][nt][i] = 0.f;

    for (int k0 = 0; k0 < K; k0 += 32) {
        #pragma unroll
        for (int i = 0; i < 4; i++) {
            int idx = t + i * 256;
            int r = idx >> 3;
            int kq = (idx & 7) * 4;
            int gr = row0 + r;
            int gk = k0 + kq;
            float4 v = make_float4(0.f, 0.f, 0.f, 0.f);
            if (gr < M) {
                if (k4 && gk + 3 < K) {
                    v = *(const float4*)&A[(size_t)gr * K + gk];
                } else {
                    float tv[4] = {0.f, 0.f, 0.f, 0.f};
                    #pragma unroll
                    for (int j = 0; j < 4; j++)
                        if (gk + j < K) tv[j] = __ldg(&A[(size_t)gr * K + gk + j]);
                    v = make_float4(tv[0], tv[1], tv[2], tv[3]);
                }
            }
            *(uint4*)&As[r][kq] = make_uint4(f2tf32(v.x), f2tf32(v.y), f2tf32(v.z), f2tf32(v.w));
        }
        #pragma unroll
        for (int i = 0; i < 4; i++) {
            int idx = t + i * 256;
            int kk = idx >> 5;
            int nq = (idx & 31) * 4;
            float4 v = make_float4(0.f, 0.f, 0.f, 0.f);
            if (k0 + kk < K) v = *(const float4*)&W[(size_t)(k0 + kk) * 128 + nq];
            *(uint4*)&Bs[kk][nq] = make_uint4(f2tf32(v.x), f2tf32(v.y), f2tf32(v.z), f2tf32(v.w));
        }
        __syncthreads();

        #pragma unroll
        for (int k8 = 0; k8 < 4; k8++) {
            int kb = k8 * 8;
            int g = lane >> 2;
            int tt = lane & 3;
            uint32_t a[2][4], b[8][2];
            #pragma unroll
            for (int mt = 0; mt < 2; mt++) {
                int ar = wm * 32 + mt * 16 + g;
                a[mt][0] = As[ar][kb + tt];
                a[mt][1] = As[ar + 8][kb + tt];
                a[mt][2] = As[ar][kb + tt + 4];
                a[mt][3] = As[ar + 8][kb + tt + 4];
            }
            #pragma unroll
            for (int nt = 0; nt < 8; nt++) {
                int bn = wn * 64 + nt * 8 + g;
                b[nt][0] = Bs[kb + tt][bn];
                b[nt][1] = Bs[kb + tt + 4][bn];
            }
            #pragma unroll
            for (int mt = 0; mt < 2; mt++)
                #pragma unroll
                for (int nt = 0; nt < 8; nt++) {
                    asm volatile(
                        "mma.sync.aligned.m16n8k8.row.col.f32.tf32.tf32.f32 "
                        "{%0,%1,%2,%3}, {%4,%5,%6,%7}, {%8,%9}, {%0,%1,%2,%3};\n"
                        : "+f"(c[mt][nt][0]), "+f"(c[mt][nt][1]),
                          "+f"(c[mt][nt][2]), "+f"(c[mt][nt][3])
                        : "r"(a[mt][0]), "r"(a[mt][1]), "r"(a[mt][2]), "r"(a[mt][3]),
                          "r"(b[nt][0]), "r"(b[nt][1]));
                }
        }
        __syncthreads();
    }

    int g = lane >> 2;
    int tt = lane & 3;
    #pragma unroll
    for (int nt = 0; nt < 8; nt++) {
        int col = wn * 64 + nt * 8 + 2 * tt;
        float b0 = 0.f, b1 = 0.f;
        if (BIAS) { b0 = __ldg(&bias[col]); b1 = __ldg(&bias[col + 1]); }
        #pragma unroll
        for (int mt = 0; mt < 2; mt++) {
            int r = row0 + wm * 32 + mt * 16 + g;
            float v0 = c[mt][nt][0] + b0;
            float v1 = c[mt][nt][1] + b1;
            float v2 = c[mt][nt][2] + b0;
            float v3 = c[mt][nt][3] + b1;
            if (RELU) {
                v0 = fmaxf(v0, 0.f); v1 = fmaxf(v1, 0.f);
                v2 = fmaxf(v2, 0.f); v3 = fmaxf(v3, 0.f);
            }
            if (r < M)     *(float2*)&C[(size_t)r * 128 + col]       = make_float2(v0, v1);
            if (r + 8 < M) *(float2*)&C[(size_t)(r + 8) * 128 + col] = make_float2(v2, v3);
        }
    }
}

// ---------------- fused 2-layer MLP: C = relu(relu(A@W1+b1)@W2+b2), N=128 ----------------
// mid tile kept in smem as tf32. Layer-2 K fixed at 128.
__global__ __launch_bounds__(256) void mlp2_tc(
    const float* __restrict__ A, const float* __restrict__ W1,
    const float* __restrict__ b1, const float* __restrict__ W2,
    const float* __restrict__ b2, float* __restrict__ C,
    int M, int K)
{
    extern __shared__ uint32_t smemu[];
    uint32_t (*As)[36]  = (uint32_t(*)[36])smemu;                    // 128*36
    uint32_t (*Bs)[132] = (uint32_t(*)[132])(smemu + 128 * 36);      // 32*132
    uint32_t (*Mid)[132]= (uint32_t(*)[132])(smemu + 128 * 36 + 32 * 132); // 128*132

    int t = threadIdx.x;
    int lane = t & 31;
    int warp = t >> 5;
    int wm = warp & 3;
    int wn = warp >> 2;
    int row0 = blockIdx.x * 128;
    bool k4 = (K & 3) == 0;
    int g = lane >> 2;
    int tt = lane & 3;

    float c[2][8][4];
    #pragma unroll
    for (int mt = 0; mt < 2; mt++)
        #pragma unroll
        for (int nt = 0; nt < 8; nt++)
            #pragma unroll
            for (int i = 0; i < 4; i++) c[mt][nt][i] = 0.f;

    // ---- phase 1: mid = relu(A@W1 + b1) ----
    for (int k0 = 0; k0 < K; k0 += 32) {
        #pragma unroll
        for (int i = 0; i < 4; i++) {
            int idx = t + i * 256;
            int r = idx >> 3;
            int kq = (idx & 7) * 4;
            int gr = row0 + r;
            int gk = k0 + kq;
            float4 v = make_float4(0.f, 0.f, 0.f, 0.f);
            if (gr < M) {
                if (k4 && gk + 3 < K) {
                    v = *(const float4*)&A[(size_t)gr * K + gk];
                } else {
                    float tv[4] = {0.f, 0.f, 0.f, 0.f};
                    #pragma unroll
                    for (int j = 0; j < 4; j++)
                        if (gk + j < K) tv[j] = __ldg(&A[(size_t)gr * K + gk + j]);
                    v = make_float4(tv[0], tv[1], tv[2], tv[3]);
                }
            }
            *(uint4*)&As[r][kq] = make_uint4(f2tf32(v.x), f2tf32(v.y), f2tf32(v.z), f2tf32(v.w));
        }
        #pragma unroll
        for (int i = 0; i < 4; i++) {
            int idx = t + i * 256;
            int kk = idx >> 5;
            int nq = (idx & 31) * 4;
            float4 v = make_float4(0.f, 0.f, 0.f, 0.f);
            if (k0 + kk < K) v = *(const float4*)&W1[(size_t)(k0 + kk) * 128 + nq];
            *(uint4*)&Bs[kk][nq] = make_uint4(f2tf32(v.x), f2tf32(v.y), f2tf32(v.z), f2tf32(v.w));
        }
        __syncthreads();
        #pragma unroll
        for (int k8 = 0; k8 < 4; k8++) {
            int kb = k8 * 8;
            uint32_t a[2][4], b[8][2];
            #pragma unroll
            for (int mt = 0; mt < 2; mt++) {
                int ar = wm * 32 + mt * 16 + g;
                a[mt][0] = As[ar][kb + tt];
                a[mt][1] = As[ar + 8][kb + tt];
                a[mt][2] = As[ar][kb + tt + 4];
                a[mt][3] = As[ar + 8][kb + tt + 4];
            }
            #pragma unroll
            for (int nt = 0; nt < 8; nt++) {
                int bn = wn * 64 + nt * 8 + g;
                b[nt][0] = Bs[kb + tt][bn];
                b[nt][1] = Bs[kb + tt + 4][bn];
            }
            #pragma unroll
            for (int mt = 0; mt < 2; mt++)
                #pragma unroll
                for (int nt = 0; nt < 8; nt++) {
                    asm volatile(
                        "mma.sync.aligned.m16n8k8.row.col.f32.tf32.tf32.f32 "
                        "{%0,%1,%2,%3}, {%4,%5,%6,%7}, {%8,%9}, {%0,%1,%2,%3};\n"
                        : "+f"(c[mt][nt][0]), "+f"(c[mt][nt][1]),
                          "+f"(c[mt][nt][2]), "+f"(c[mt][nt][3])
                        : "r"(a[mt][0]), "r"(a[mt][1]), "r"(a[mt][2]), "r"(a[mt][3]),
                          "r"(b[nt][0]), "r"(b[nt][1]));
                }
        }
        __syncthreads();
    }

    // epilogue 1 -> Mid (tf32)
    #pragma unroll
    for (int nt = 0; nt < 8; nt++) {
        int col = wn * 64 + nt * 8 + 2 * tt;
        float bb0 = __ldg(&b1[col]);
        float bb1 = __ldg(&b1[col + 1]);
        #pragma unroll
        for (int mt = 0; mt < 2; mt++) {
            int r = wm * 32 + mt * 16 + g;
            Mid[r][col]         = f2tf32(fmaxf(c[mt][nt][0] + bb0, 0.f));
            Mid[r][col + 1]     = f2tf32(fmaxf(c[mt][nt][1] + bb1, 0.f));
            Mid[r + 8][col]     = f2tf32(fmaxf(c[mt][nt][2] + bb0, 0.f));
            Mid[r + 8][col + 1] = f2tf32(fmaxf(c[mt][nt][3] + bb1, 0.f));
            c[mt][nt][0] = 0.f; c[mt][nt][1] = 0.f; c[mt][nt][2] = 0.f; c[mt][nt][3] = 0.f;
        }
    }
    __syncthreads();

    // ---- phase 2: C = relu(Mid@W2 + b2), K=128 ----
    for (int k0 = 0; k0 < 128; k0 += 32) {
        #pragma unroll
        for (int i = 0; i < 4; i++) {
            int idx = t + i * 256;
            int kk = idx >> 5;
            int nq = (idx & 31) * 4;
            float4 v = *(const float4*)&W2[(size_t)(k0 + kk) * 128 + nq];
            *(uint4*)&Bs[kk][nq] = make_uint4(f2tf32(v.x), f2tf32(v.y), f2tf32(v.z), f2tf32(v.w));
        }
        __syncthreads();
        #pragma unroll
        for (int k8 = 0; k8 < 4; k8++) {
            int kb = k0 + k8 * 8;
            uint32_t a[2][4], b[8][2];
            #pragma unroll
            for (int mt = 0; mt < 2; mt++) {
                int ar = wm * 32 + mt * 16 + g;
                a[mt][0] = Mid[ar][kb + tt];
                a[mt][1] = Mid[ar + 8][kb + tt];
                a[mt][2] = Mid[ar][kb + tt + 4];
                a[mt][3] = Mid[ar + 8][kb + tt + 4];
            }
            #pragma unroll
            for (int nt = 0; nt < 8; nt++) {
                int bn = wn * 64 + nt * 8 + g;
                b[nt][0] = Bs[(k8 * 8) + tt][bn];
                b[nt][1] = Bs[(k8 * 8) + tt + 4][bn];
            }
            #pragma unroll
            for (int mt = 0; mt < 2; mt++)
                #pragma unroll
                for (int nt = 0; nt < 8; nt++) {
                    asm volatile(
                        "mma.sync.aligned.m16n8k8.row.col.f32.tf32.tf32.f32 "
                        "{%0,%1,%2,%3}, {%4,%5,%6,%7}, {%8,%9}, {%0,%1,%2,%3};\n"
                        : "+f"(c[mt][nt][0]), "+f"(c[mt][nt][1]),
                          "+f"(c[mt][nt][2]), "+f"(c[mt][nt][3])
                        : "r"(a[mt][0]), "r"(a[mt][1]), "r"(a[mt][2]), "r"(a[mt][3]),
                          "r"(b[nt][0]), "r"(b[nt][1]));
                }
        }
        __syncthreads();
    }

    #pragma unroll
    for (int nt = 0; nt < 8; nt++) {
        int col = wn * 64 + nt * 8 + 2 * tt;
        float bb0 = __ldg(&b2[col]);
        float bb1 = __ldg(&b2[col + 1]);
        #pragma unroll
        for (int mt = 0; mt < 2; mt++) {
            int r = row0 + wm * 32 + mt * 16 + g;
            float v0 = fmaxf(c[mt][nt][0] + bb0, 0.f);
            float v1 = fmaxf(c[mt][nt][1] + bb1, 0.f);
            float v2 = fmaxf(c[mt][nt][2] + bb0, 0.f);
            float v3 = fmaxf(c[mt][nt][3] + bb1, 0.f);
            if (r < M)     *(float2*)&C[(size_t)r * 128 + col]       = make_float2(v0, v1);
            if (r + 8 < M) *(float2*)&C[(size_t)(r + 8) * 128 + col] = make_float2(v2, v3);
        }
    }
}

// ---------------- decomposed edge MLP output stage ----------------
__global__ __launch_bounds__(512) void edge_out(
    const float* __restrict__ Arow, const float* __restrict__ Brow,
    const float* __restrict__ eattr,
    const float* __restrict__ w1g,
    const float* __restrict__ b1g,
    const float* __restrict__ w2g, const float* __restrict__ b2g,
    float* __restrict__ out)
{
    __shared__ __align__(16) float wc[EDGE_DIM * 128];
    __shared__ __align__(16) float b1s[128];
    __shared__ float w2s[256];
    __shared__ float b2s[2];

    int t = threadIdx.x;
    for (int i = t; i < EDGE_DIM * 128; i += 512) wc[i] = w1g[256 * 128 + i];
    if (t < 128) b1s[t] = b1g[t];
    if (t < 256) w2s[t] = w2g[t];
    if (t < 2)   b2s[t] = b2g[t];
    __syncthreads();

    int lane = t & 31;
    int w = t >> 5;
    int gw = blockIdx.x * 16 + w;
    int ngw = gridDim.x * 16;

    const float4* A4 = (const float4*)Arow;
    const float4* B4 = (const float4*)Brow;
    const float4* wc4 = (const float4*)wc;

    float4 bb = *(const float4*)&b1s[lane * 4];
    float w20 = w2s[(lane * 4 + 0) * 2 + 0], w21 = w2s[(lane * 4 + 0) * 2 + 1];
    float w22 = w2s[(lane * 4 + 1) * 2 + 0], w23 = w2s[(lane * 4 + 1) * 2 + 1];
    float w24 = w2s[(lane * 4 + 2) * 2 + 0], w25 = w2s[(lane * 4 + 2) * 2 + 1];
    float w26 = w2s[(lane * 4 + 3) * 2 + 0], w27 = w2s[(lane * 4 + 3) * 2 + 1];
    float bo0 = b2s[0], bo1 = b2s[1];

    for (int p = gw; p < N_EDGES / 2; p += ngw) {
        int e0 = 2 * p, e1 = e0 + 1;
        int s0 = g_src[e0], d0 = g_dst[e0];
        int s1 = g_src[e1], d1 = g_dst[e1];
        float4 va0 = A4[(size_t)s0 * 32 + lane];
        float4 vb0 = B4[(size_t)d0 * 32 + lane];
        float4 va1 = A4[(size_t)s1 * 32 + lane];
        float4 vb1 = B4[(size_t)d1 * 32 + lane];

        float av = (lane < 14) ? eattr[(size_t)e0 * EDGE_DIM + lane] : 0.f;
        float a0[7], a1[7];
        #pragma unroll
        for (int c = 0; c < 7; c++) {
            a0[c] = __shfl_sync(0xffffffffu, av, c);
            a1[c] = __shfl_sync(0xffffffffu, av, c + 7);
        }

        float4 c0 = make_float4(0.f, 0.f, 0.f, 0.f);
        float4 c1 = make_float4(0.f, 0.f, 0.f, 0.f);
        #pragma unroll
        for (int k = 0; k < EDGE_DIM; k++) {
            float4 wv = wc4[k * 32 + lane];
            c0.x = fmaf(a0[k], wv.x, c0.x); c1.x = fmaf(a1[k], wv.x, c1.x);
            c0.y = fmaf(a0[k], wv.y, c0.y); c1.y = fmaf(a1[k], wv.y, c1.y);
            c0.z = fmaf(a0[k], wv.z, c0.z); c1.z = fmaf(a1[k], wv.z, c1.z);
            c0.w = fmaf(a0[k], wv.w, c0.w); c1.w = fmaf(a1[k], wv.w, c1.w);
        }

        float h00 = fmaxf(va0.x + vb0.x + c0.x + bb.x, 0.f);
        float h01 = fmaxf(va0.y + vb0.y + c0.y + bb.y, 0.f);
        float h02 = fmaxf(va0.z + vb0.z + c0.z + bb.z, 0.f);
        float h03 = fmaxf(va0.w + vb0.w + c0.w + bb.w, 0.f);
        float h10 = fmaxf(va1.x + vb1.x + c1.x + bb.x, 0.f);
        float h11 = fmaxf(va1.y + vb1.y + c1.y + bb.y, 0.f);
        float h12 = fmaxf(va1.z + vb1.z + c1.z + bb.z, 0.f);
        float h13 = fmaxf(va1.w + vb1.w + c1.w + bb.w, 0.f);

        float s0o = h00 * w20 + h01 * w22 + h02 * w24 + h03 * w26;
        float s1o = h00 * w21 + h01 * w23 + h02 * w25 + h03 * w27;
        float s2o = h10 * w20 + h11 * w22 + h12 * w24 + h13 * w26;
        float s3o = h10 * w21 + h11 * w23 + h12 * w25 + h13 * w27;

        #pragma unroll
        for (int off = 16; off; off >>= 1) {
            s0o += __shfl_down_sync(0xffffffffu, s0o, off);
            s1o += __shfl_down_sync(0xffffffffu, s1o, off);
            s2o += __shfl_down_sync(0xffffffffu, s2o, off);
            s3o += __shfl_down_sync(0xffffffffu, s3o, off);
        }
        if (lane == 0) {
            *(float2*)&out[(size_t)e0 * 2] = make_float2(s0o + bo0, s1o + bo1);
            *(float2*)&out[(size_t)e1 * 2] = make_float2(s2o + bo0, s3o + bo1);
        }
    }
}

// ---------------- launch ----------------
extern "C" void kernel_launch(void* const* d_in, const int* in_sizes, int n_in,
                              void* d_out, int out_size) {
    const float* x    = (const float*)d_in[0];
    const void*  ei   = d_in[1];
    const float* ea   = (const float*)d_in[2];
    const float* e1w  = (const float*)d_in[3];
    const float* e1b  = (const float*)d_in[4];
    const float* m1w1 = (const float*)d_in[5];
    const float* m1b1 = (const float*)d_in[6];
    const float* m1w2 = (const float*)d_in[7];
    const float* m1b2 = (const float*)d_in[8];
    const float* e2w  = (const float*)d_in[9];
    const float* e2b  = (const float*)d_in[10];
    const float* m2w1 = (const float*)d_in[11];
    const float* m2b1 = (const float*)d_in[12];
    const float* m2w2 = (const float*)d_in[13];
    const float* m2b2 = (const float*)d_in[14];
    const float* emw1 = (const float*)d_in[15];
    const float* emb1 = (const float*)d_in[16];
    const float* emw2 = (const float*)d_in[17];
    const float* emb2 = (const float*)d_in[18];
    float* out = (float*)d_out;

    float *aggr1, *h1, *aggr2, *h2;
    cudaGetSymbolAddress((void**)&aggr1, g_aggr1);
    cudaGetSymbolAddress((void**)&h1,    g_h1);
    cudaGetSymbolAddress((void**)&aggr2, g_aggr2);
    cudaGetSymbolAddress((void**)&h2,    g_h2);
    float* gA = aggr1;                                  // reuse aggr1 after conv1
    float* gB = aggr1 + (size_t)N_NODES * HID;

    size_t mlp_smem = (size_t)(128 * 36 + 32 * 132 + 128 * 132) * 4;
    cudaFuncSetAttribute(mlp2_tc, cudaFuncAttributeMaxDynamicSharedMemorySize, (int)mlp_smem);

    int gemm_grid = (N_NODES + 127) / 128;

    detect_idx<<<1, 32>>>(ei);
    convert_idx<<<1024, 256>>>(ei);

    // conv1
    copy4<<<4096, 256>>>(x, aggr1, (N_NODES * NODE_IN) / 4);
    edge_msg387<<<2048, 256>>>(x, ea, e1w, e1b, aggr1);
    mlp2_tc<<<gemm_grid, 256, mlp_smem>>>(aggr1, m1w1, m1b1, m1w2, m1b2, h1, N_NODES, NODE_IN);

    // conv2
    copy4<<<2048, 256>>>(h1, aggr2, (N_NODES * HID) / 4);
    edge_msg128<<<2048, 256>>>(h1, ea, e2w, e2b, aggr2);
    mlp2_tc<<<gemm_grid, 256, mlp_smem>>>(aggr2, m2w1, m2b1, m2w2, m2b2, h2, N_NODES, HID);

    // edge MLP (decomposed)
    gemm_tc<false, false><<<gemm_grid, 256>>>(h2, emw1, nullptr, gA, N_NODES, HID);
    gemm_tc<false, false><<<gemm_grid, 256>>>(h2, emw1 + 128 * 128, nullptr, gB, N_NODES, HID);
    edge_out<<<296, 512>>>(gA, gB, ea, emw1, emb1, emw2, emb2, out);
}

// round 8
// speedup vs baseline: 1.4136x; 1.4136x over previous
#include <cuda_runtime.h>
#include <stdint.h>
#include <stddef.h>

#define N_NODES 100000
#define N_EDGES 600000
#define NODE_IN 387
#define HID 128
#define EDGE_DIM 7

// ---------------- device scratch (allocation-free) ----------------
__device__ float g_aggr1[(size_t)N_NODES * NODE_IN];   // 155 MB (reused as gA/gB later)
__device__ float g_h1   [(size_t)N_NODES * HID];
__device__ float g_aggr2[(size_t)N_NODES * HID];
__device__ float g_h2   [(size_t)N_NODES * HID];
__device__ int   g_src[N_EDGES];
__device__ int   g_dst[N_EDGES];

// ---------------- index canonicalization (per-block dtype detection) ----------------
__global__ void convert_idx(const void* ei) {
    __shared__ int s_is64;
    if (threadIdx.x == 0) {
        const long long* p = (const long long*)ei;
        int ok = 1;
        #pragma unroll 4
        for (int i = 0; i < 256; i++) {
            long long v = p[i];
            if (v < 0 || v >= (long long)N_NODES) { ok = 0; break; }
        }
        s_is64 = ok;
    }
    __syncthreads();
    int is64 = s_is64;
    int stride = gridDim.x * blockDim.x;
    for (int i = blockIdx.x * blockDim.x + threadIdx.x; i < 2 * N_EDGES; i += stride) {
        int v;
        if (is64) v = (int)((const long long*)ei)[i];
        else      v = ((const int*)ei)[i];
        if (i < N_EDGES) g_src[i] = v;
        else             g_dst[i - N_EDGES] = v;
    }
}

// ---------------- vectorized copy ----------------
__global__ void copy4(const float* __restrict__ src, float* __restrict__ dst, int n4) {
    int stride = gridDim.x * blockDim.x;
    const float4* s = (const float4*)src;
    float4* d = (float4*)dst;
    for (int i = blockIdx.x * blockDim.x + threadIdx.x; i < n4; i += stride)
        d[i] = s[i];
}

// ---------------- conv1 message+scatter: one 128-feature chunk per pass ----------------
// Pass covers features [DLO, DLO+128); REM adds features 384..386 (pass 3 only).
// Stride-32 access: lane handles f = lane + 32*i  (contiguous 128B per LDG/RED instr).
template<int DLO, bool REM>
__global__ __launch_bounds__(256) void edge_msg_pass(
    const float* __restrict__ xin, const float* __restrict__ eattr,
    const float* __restrict__ wg, const float* __restrict__ bg,
    float* __restrict__ aggr)
{
    __shared__ float sw[EDGE_DIM * 128];
    __shared__ float sb[128];
    __shared__ float swr[EDGE_DIM * 4];
    __shared__ float sbr[4];
    for (int i = threadIdx.x; i < EDGE_DIM * 128; i += 256) {
        int c = i >> 7, j = i & 127;
        sw[i] = wg[c * NODE_IN + DLO + j];
    }
    if (threadIdx.x < 128) sb[threadIdx.x] = bg[DLO + threadIdx.x];
    if (REM) {
        if (threadIdx.x < EDGE_DIM * 3) {
            int c = threadIdx.x / 3, j = threadIdx.x % 3;
            swr[c * 4 + j] = wg[c * NODE_IN + 384 + j];
        }
        if (threadIdx.x < 3) sbr[threadIdx.x] = bg[384 + threadIdx.x];
    }
    __syncthreads();

    int lane = threadIdx.x & 31;
    int gw = (blockIdx.x * 256 + threadIdx.x) >> 5;
    int nw = (gridDim.x * 256) >> 5;

    for (int p = gw; p < N_EDGES / 2; p += nw) {
        int e0 = 2 * p;
        int2 ss = *(const int2*)&g_src[e0];
        int2 dd = *(const int2*)&g_dst[e0];
        float av = (lane < 14) ? eattr[(size_t)e0 * EDGE_DIM + lane] : 0.f;
        float a0[7], a1[7];
        #pragma unroll
        for (int c = 0; c < 7; c++) {
            a0[c] = __shfl_sync(0xffffffffu, av, c);
            a1[c] = __shfl_sync(0xffffffffu, av, c + 7);
        }

        const float* xs0 = xin + (size_t)ss.x * NODE_IN + DLO;
        const float* xs1 = xin + (size_t)ss.y * NODE_IN + DLO;
        float* ag0 = aggr + (size_t)dd.x * NODE_IN + DLO;
        float* ag1 = aggr + (size_t)dd.y * NODE_IN + DLO;

        #pragma unroll
        for (int i = 0; i < 4; i++) {
            int f = lane + 32 * i;
            float m0 = sb[f] + __ldg(&xs0[f]);
            float m1 = sb[f] + __ldg(&xs1[f]);
            #pragma unroll
            for (int c = 0; c < 7; c++) {
                float wv = sw[c * 128 + f];
                m0 = fmaf(a0[c], wv, m0);
                m1 = fmaf(a1[c], wv, m1);
            }
            atomicAdd(&ag0[f], fmaxf(m0, 0.f));
            atomicAdd(&ag1[f], fmaxf(m1, 0.f));
        }
        if (REM) {
            if (lane < 3) {
                int f = 128 + lane;       // global feature 384+lane
                float m0 = sbr[lane] + __ldg(&xs0[f]);
                float m1 = sbr[lane] + __ldg(&xs1[f]);
                #pragma unroll
                for (int c = 0; c < 7; c++) {
                    float wv = swr[c * 4 + lane];
                    m0 = fmaf(a0[c], wv, m0);
                    m1 = fmaf(a1[c], wv, m1);
                }
                atomicAdd(&ag0[f], fmaxf(m0, 0.f));
                atomicAdd(&ag1[f], fmaxf(m1, 0.f));
            }
        }
    }
}

// ---------------- conv2 message+scatter (D=128, stride-32) ----------------
__global__ __launch_bounds__(256) void edge_msg128(
    const float* __restrict__ xin, const float* __restrict__ eattr,
    const float* __restrict__ wg, const float* __restrict__ bg,
    float* __restrict__ aggr)
{
    __shared__ float sw[EDGE_DIM * HID];
    __shared__ float sb[HID];
    for (int i = threadIdx.x; i < EDGE_DIM * HID; i += 256) sw[i] = wg[i];
    if (threadIdx.x < HID) sb[threadIdx.x] = bg[threadIdx.x];
    __syncthreads();

    int lane = threadIdx.x & 31;
    int gw = (blockIdx.x * 256 + threadIdx.x) >> 5;
    int nw = (gridDim.x * 256) >> 5;

    for (int p = gw; p < N_EDGES / 2; p += nw) {
        int e0 = 2 * p;
        int2 ss = *(const int2*)&g_src[e0];
        int2 dd = *(const int2*)&g_dst[e0];
        float av = (lane < 14) ? eattr[(size_t)e0 * EDGE_DIM + lane] : 0.f;
        float a0[7], a1[7];
        #pragma unroll
        for (int c = 0; c < 7; c++) {
            a0[c] = __shfl_sync(0xffffffffu, av, c);
            a1[c] = __shfl_sync(0xffffffffu, av, c + 7);
        }

        const float* xs0 = xin + (size_t)ss.x * HID;
        const float* xs1 = xin + (size_t)ss.y * HID;
        float* ag0 = aggr + (size_t)dd.x * HID;
        float* ag1 = aggr + (size_t)dd.y * HID;

        #pragma unroll
        for (int i = 0; i < 4; i++) {
            int f = lane + 32 * i;
            float m0 = sb[f] + __ldg(&xs0[f]);
            float m1 = sb[f] + __ldg(&xs1[f]);
            #pragma unroll
            for (int c = 0; c < 7; c++) {
                float wv = sw[c * 128 + f];
                m0 = fmaf(a0[c], wv, m0);
                m1 = fmaf(a1[c], wv, m1);
            }
            atomicAdd(&ag0[f], fmaxf(m0, 0.f));
            atomicAdd(&ag1[f], fmaxf(m1, 0.f));
        }
    }
}

// ---------------- tf32 helpers ----------------
__device__ __forceinline__ uint32_t f2tf32(float f) {
    uint32_t u;
    asm("cvt.rna.tf32.f32 %0, %1;" : "=r"(u) : "f"(f));
    return u;
}

// ---------------- dual tf32 GEMM: gA = A@Wa, gB = A@Wb  (K=128 fixed) ----------------
__global__ __launch_bounds__(256) void gemm_tc2(
    const float* __restrict__ A, const float* __restrict__ W,   // W = em_w1 base
    float* __restrict__ C0, float* __restrict__ C1, int M)
{
    __shared__ uint32_t As[128][36];
    __shared__ uint32_t Bs[32][132];

    const float* Wb = W + (size_t)blockIdx.y * 128 * 128;
    float* C = blockIdx.y ? C1 : C0;

    int t = threadIdx.x;
    int lane = t & 31;
    int warp = t >> 5;
    int wm = warp & 3;
    int wn = warp >> 2;
    int row0 = blockIdx.x * 128;
    int g = lane >> 2;
    int tt = lane & 3;

    float c[2][8][4];
    #pragma unroll
    for (int mt = 0; mt < 2; mt++)
        #pragma unroll
        for (int nt = 0; nt < 8; nt++)
            #pragma unroll
            for (int i = 0; i < 4; i++) c[mt][nt][i] = 0.f;

    for (int k0 = 0; k0 < 128; k0 += 32) {
        #pragma unroll
        for (int i = 0; i < 4; i++) {
            int idx = t + i * 256;
            int r = idx >> 3;
            int kq = (idx & 7) * 4;
            int gr = row0 + r;
            float4 v = make_float4(0.f, 0.f, 0.f, 0.f);
            if (gr < M) v = *(const float4*)&A[(size_t)gr * 128 + k0 + kq];
            *(uint4*)&As[r][kq] = make_uint4(f2tf32(v.x), f2tf32(v.y), f2tf32(v.z), f2tf32(v.w));
        }
        #pragma unroll
        for (int i = 0; i < 4; i++) {
            int idx = t + i * 256;
            int kk = idx >> 5;
            int nq = (idx & 31) * 4;
            float4 v = *(const float4*)&Wb[(size_t)(k0 + kk) * 128 + nq];
            *(uint4*)&Bs[kk][nq] = make_uint4(f2tf32(v.x), f2tf32(v.y), f2tf32(v.z), f2tf32(v.w));
        }
        __syncthreads();
        #pragma unroll
        for (int k8 = 0; k8 < 4; k8++) {
            int kb = k8 * 8;
            uint32_t a[2][4], b[8][2];
            #pragma unroll
            for (int mt = 0; mt < 2; mt++) {
                int ar = wm * 32 + mt * 16 + g;
                a[mt][0] = As[ar][kb + tt];
                a[mt][1] = As[ar + 8][kb + tt];
                a[mt][2] = As[ar][kb + tt + 4];
                a[mt][3] = As[ar + 8][kb + tt + 4];
            }
            #pragma unroll
            for (int nt = 0; nt < 8; nt++) {
                int bn = wn * 64 + nt * 8 + g;
                b[nt][0] = Bs[kb + tt][bn];
                b[nt][1] = Bs[kb + tt + 4][bn];
            }
            #pragma unroll
            for (int mt = 0; mt < 2; mt++)
                #pragma unroll
                for (int nt = 0; nt < 8; nt++) {
                    asm volatile(
                        "mma.sync.aligned.m16n8k8.row.col.f32.tf32.tf32.f32 "
                        "{%0,%1,%2,%3}, {%4,%5,%6,%7}, {%8,%9}, {%0,%1,%2,%3};\n"
                        : "+f"(c[mt][nt][0]), "+f"(c[mt][nt][1]),
                          "+f"(c[mt][nt][2]), "+f"(c[mt][nt][3])
                        : "r"(a[mt][0]), "r"(a[mt][1]), "r"(a[mt][2]), "r"(a[mt][3]),
                          "r"(b[nt][0]), "r"(b[nt][1]));
                }
        }
        __syncthreads();
    }

    #pragma unroll
    for (int nt = 0; nt < 8; nt++) {
        int col = wn * 64 + nt * 8 + 2 * tt;
        #pragma unroll
        for (int mt = 0; mt < 2; mt++) {
            int r = row0 + wm * 32 + mt * 16 + g;
            if (r < M)
                *(float2*)&C[(size_t)r * 128 + col] = make_float2(c[mt][nt][0], c[mt][nt][1]);
            if (r + 8 < M)
                *(float2*)&C[(size_t)(r + 8) * 128 + col] = make_float2(c[mt][nt][2], c[mt][nt][3]);
        }
    }
}

// ---------------- fused 2-layer MLP: C = relu(relu(A@W1+b1)@W2+b2), N=128 ----------------
__global__ __launch_bounds__(256) void mlp2_tc(
    const float* __restrict__ A, const float* __restrict__ W1,
    const float* __restrict__ b1, const float* __restrict__ W2,
    const float* __restrict__ b2, float* __restrict__ C,
    int M, int K)
{
    extern __shared__ uint32_t smemu[];
    uint32_t (*As)[36]  = (uint32_t(*)[36])smemu;
    uint32_t (*Bs)[132] = (uint32_t(*)[132])(smemu + 128 * 36);
    uint32_t (*Mid)[132]= (uint32_t(*)[132])(smemu + 128 * 36 + 32 * 132);

    int t = threadIdx.x;
    int lane = t & 31;
    int warp = t >> 5;
    int wm = warp & 3;
    int wn = warp >> 2;
    int row0 = blockIdx.x * 128;
    bool k4 = (K & 3) == 0;
    int g = lane >> 2;
    int tt = lane & 3;

    float c[2][8][4];
    #pragma unroll
    for (int mt = 0; mt < 2; mt++)
        #pragma unroll
        for (int nt = 0; nt < 8; nt++)
            #pragma unroll
            for (int i = 0; i < 4; i++) c[mt][nt][i] = 0.f;

    for (int k0 = 0; k0 < K; k0 += 32) {
        #pragma unroll
        for (int i = 0; i < 4; i++) {
            int idx = t + i * 256;
            int r = idx >> 3;
            int kq = (idx & 7) * 4;
            int gr = row0 + r;
            int gk = k0 + kq;
            float4 v = make_float4(0.f, 0.f, 0.f, 0.f);
            if (gr < M) {
                if (k4 && gk + 3 < K) {
                    v = *(const float4*)&A[(size_t)gr * K + gk];
                } else {
                    float tv[4] = {0.f, 0.f, 0.f, 0.f};
                    #pragma unroll
                    for (int j = 0; j < 4; j++)
                        if (gk + j < K) tv[j] = __ldg(&A[(size_t)gr * K + gk + j]);
                    v = make_float4(tv[0], tv[1], tv[2], tv[3]);
                }
            }
            *(uint4*)&As[r][kq] = make_uint4(f2tf32(v.x), f2tf32(v.y), f2tf32(v.z), f2tf32(v.w));
        }
        #pragma unroll
        for (int i = 0; i < 4; i++) {
            int idx = t + i * 256;
            int kk = idx >> 5;
            int nq = (idx & 31) * 4;
            float4 v = make_float4(0.f, 0.f, 0.f, 0.f);
            if (k0 + kk < K) v = *(const float4*)&W1[(size_t)(k0 + kk) * 128 + nq];
            *(uint4*)&Bs[kk][nq] = make_uint4(f2tf32(v.x), f2tf32(v.y), f2tf32(v.z), f2tf32(v.w));
        }
        __syncthreads();
        #pragma unroll
        for (int k8 = 0; k8 < 4; k8++) {
            int kb = k8 * 8;
            uint32_t a[2][4], b[8][2];
            #pragma unroll
            for (int mt = 0; mt < 2; mt++) {
                int ar = wm * 32 + mt * 16 + g;
                a[mt][0] = As[ar][kb + tt];
                a[mt][1] = As[ar + 8][kb + tt];
                a[mt][2] = As[ar][kb + tt + 4];
                a[mt][3] = As[ar + 8][kb + tt + 4];
            }
            #pragma unroll
            for (int nt = 0; nt < 8; nt++) {
                int bn = wn * 64 + nt * 8 + g;
                b[nt][0] = Bs[kb + tt][bn];
                b[nt][1] = Bs[kb + tt + 4][bn];
            }
            #pragma unroll
            for (int mt = 0; mt < 2; mt++)
                #pragma unroll
                for (int nt = 0; nt < 8; nt++) {
                    asm volatile(
                        "mma.sync.aligned.m16n8k8.row.col.f32.tf32.tf32.f32 "
                        "{%0,%1,%2,%3}, {%4,%5,%6,%7}, {%8,%9}, {%0,%1,%2,%3};\n"
                        : "+f"(c[mt][nt][0]), "+f"(c[mt][nt][1]),
                          "+f"(c[mt][nt][2]), "+f"(c[mt][nt][3])
                        : "r"(a[mt][0]), "r"(a[mt][1]), "r"(a[mt][2]), "r"(a[mt][3]),
                          "r"(b[nt][0]), "r"(b[nt][1]));
                }
        }
        __syncthreads();
    }

    #pragma unroll
    for (int nt = 0; nt < 8; nt++) {
        int col = wn * 64 + nt * 8 + 2 * tt;
        float bb0 = __ldg(&b1[col]);
        float bb1 = __ldg(&b1[col + 1]);
        #pragma unroll
        for (int mt = 0; mt < 2; mt++) {
            int r = wm * 32 + mt * 16 + g;
            Mid[r][col]         = f2tf32(fmaxf(c[mt][nt][0] + bb0, 0.f));
            Mid[r][col + 1]     = f2tf32(fmaxf(c[mt][nt][1] + bb1, 0.f));
            Mid[r + 8][col]     = f2tf32(fmaxf(c[mt][nt][2] + bb0, 0.f));
            Mid[r + 8][col + 1] = f2tf32(fmaxf(c[mt][nt][3] + bb1, 0.f));
            c[mt][nt][0] = 0.f; c[mt][nt][1] = 0.f; c[mt][nt][2] = 0.f; c[mt][nt][3] = 0.f;
        }
    }
    __syncthreads();

    for (int k0 = 0; k0 < 128; k0 += 32) {
        #pragma unroll
        for (int i = 0; i < 4; i++) {
            int idx = t + i * 256;
            int kk = idx >> 5;
            int nq = (idx & 31) * 4;
            float4 v = *(const float4*)&W2[(size_t)(k0 + kk) * 128 + nq];
            *(uint4*)&Bs[kk][nq] = make_uint4(f2tf32(v.x), f2tf32(v.y), f2tf32(v.z), f2tf32(v.w));
        }
        __syncthreads();
        #pragma unroll
        for (int k8 = 0; k8 < 4; k8++) {
            int kb = k0 + k8 * 8;
            uint32_t a[2][4], b[8][2];
            #pragma unroll
            for (int mt = 0; mt < 2; mt++) {
                int ar = wm * 32 + mt * 16 + g;
                a[mt][0] = Mid[ar][kb + tt];
                a[mt][1] = Mid[ar + 8][kb + tt];
                a[mt][2] = Mid[ar][kb + tt + 4];
                a[mt][3] = Mid[ar + 8][kb + tt + 4];
            }
            #pragma unroll
            for (int nt = 0; nt < 8; nt++) {
                int bn = wn * 64 + nt * 8 + g;
                b[nt][0] = Bs[(k8 * 8) + tt][bn];
                b[nt][1] = Bs[(k8 * 8) + tt + 4][bn];
            }
            #pragma unroll
            for (int mt = 0; mt < 2; mt++)
                #pragma unroll
                for (int nt = 0; nt < 8; nt++) {
                    asm volatile(
                        "mma.sync.aligned.m16n8k8.row.col.f32.tf32.tf32.f32 "
                        "{%0,%1,%2,%3}, {%4,%5,%6,%7}, {%8,%9}, {%0,%1,%2,%3};\n"
                        : "+f"(c[mt][nt][0]), "+f"(c[mt][nt][1]),
                          "+f"(c[mt][nt][2]), "+f"(c[mt][nt][3])
                        : "r"(a[mt][0]), "r"(a[mt][1]), "r"(a[mt][2]), "r"(a[mt][3]),
                          "r"(b[nt][0]), "r"(b[nt][1]));
                }
        }
        __syncthreads();
    }

    #pragma unroll
    for (int nt = 0; nt < 8; nt++) {
        int col = wn * 64 + nt * 8 + 2 * tt;
        float bb0 = __ldg(&b2[col]);
        float bb1 = __ldg(&b2[col + 1]);
        #pragma unroll
        for (int mt = 0; mt < 2; mt++) {
            int r = row0 + wm * 32 + mt * 16 + g;
            float v0 = fmaxf(c[mt][nt][0] + bb0, 0.f);
            float v1 = fmaxf(c[mt][nt][1] + bb1, 0.f);
            float v2 = fmaxf(c[mt][nt][2] + bb0, 0.f);
            float v3 = fmaxf(c[mt][nt][3] + bb1, 0.f);
            if (r < M)     *(float2*)&C[(size_t)r * 128 + col]       = make_float2(v0, v1);
            if (r + 8 < M) *(float2*)&C[(size_t)(r + 8) * 128 + col] = make_float2(v2, v3);
        }
    }
}

// ---------------- decomposed edge MLP output stage ----------------
__global__ __launch_bounds__(512) void edge_out(
    const float* __restrict__ Arow, const float* __restrict__ Brow,
    const float* __restrict__ eattr,
    const float* __restrict__ w1g,
    const float* __restrict__ b1g,
    const float* __restrict__ w2g, const float* __restrict__ b2g,
    float* __restrict__ out)
{
    __shared__ __align__(16) float wc[EDGE_DIM * 128];
    __shared__ __align__(16) float b1s[128];
    __shared__ float w2s[256];
    __shared__ float b2s[2];

    int t = threadIdx.x;
    for (int i = t; i < EDGE_DIM * 128; i += 512) wc[i] = w1g[256 * 128 + i];
    if (t < 128) b1s[t] = b1g[t];
    if (t < 256) w2s[t] = w2g[t];
    if (t < 2)   b2s[t] = b2g[t];
    __syncthreads();

    int lane = t & 31;
    int w = t >> 5;
    int gw = blockIdx.x * 16 + w;
    int ngw = gridDim.x * 16;

    const float4* A4 = (const float4*)Arow;
    const float4* B4 = (const float4*)Brow;
    const float4* wc4 = (const float4*)wc;

    float4 bb = *(const float4*)&b1s[lane * 4];
    float w20 = w2s[(lane * 4 + 0) * 2 + 0], w21 = w2s[(lane * 4 + 0) * 2 + 1];
    float w22 = w2s[(lane * 4 + 1) * 2 + 0], w23 = w2s[(lane * 4 + 1) * 2 + 1];
    float w24 = w2s[(lane * 4 + 2) * 2 + 0], w25 = w2s[(lane * 4 + 2) * 2 + 1];
    float w26 = w2s[(lane * 4 + 3) * 2 + 0], w27 = w2s[(lane * 4 + 3) * 2 + 1];
    float bo0 = b2s[0], bo1 = b2s[1];

    for (int p = gw; p < N_EDGES / 2; p += ngw) {
        int e0 = 2 * p, e1 = e0 + 1;
        int2 ss = *(const int2*)&g_src[e0];
        int2 dd = *(const int2*)&g_dst[e0];
        float4 va0 = A4[(size_t)ss.x * 32 + lane];
        float4 vb0 = B4[(size_t)dd.x * 32 + lane];
        float4 va1 = A4[(size_t)ss.y * 32 + lane];
        float4 vb1 = B4[(size_t)dd.y * 32 + lane];

        float av = (lane < 14) ? eattr[(size_t)e0 * EDGE_DIM + lane] : 0.f;
        float a0[7], a1[7];
        #pragma unroll
        for (int c = 0; c < 7; c++) {
            a0[c] = __shfl_sync(0xffffffffu, av, c);
            a1[c] = __shfl_sync(0xffffffffu, av, c + 7);
        }

        float4 c0 = make_float4(0.f, 0.f, 0.f, 0.f);
        float4 c1 = make_float4(0.f, 0.f, 0.f, 0.f);
        #pragma unroll
        for (int k = 0; k < EDGE_DIM; k++) {
            float4 wv = wc4[k * 32 + lane];
            c0.x = fmaf(a0[k], wv.x, c0.x); c1.x = fmaf(a1[k], wv.x, c1.x);
            c0.y = fmaf(a0[k], wv.y, c0.y); c1.y = fmaf(a1[k], wv.y, c1.y);
            c0.z = fmaf(a0[k], wv.z, c0.z); c1.z = fmaf(a1[k], wv.z, c1.z);
            c0.w = fmaf(a0[k], wv.w, c0.w); c1.w = fmaf(a1[k], wv.w, c1.w);
        }

        float h00 = fmaxf(va0.x + vb0.x + c0.x + bb.x, 0.f);
        float h01 = fmaxf(va0.y + vb0.y + c0.y + bb.y, 0.f);
        float h02 = fmaxf(va0.z + vb0.z + c0.z + bb.z, 0.f);
        float h03 = fmaxf(va0.w + vb0.w + c0.w + bb.w, 0.f);
        float h10 = fmaxf(va1.x + vb1.x + c1.x + bb.x, 0.f);
        float h11 = fmaxf(va1.y + vb1.y + c1.y + bb.y, 0.f);
        float h12 = fmaxf(va1.z + vb1.z + c1.z + bb.z, 0.f);
        float h13 = fmaxf(va1.w + vb1.w + c1.w + bb.w, 0.f);

        float s0o = h00 * w20 + h01 * w22 + h02 * w24 + h03 * w26;
        float s1o = h00 * w21 + h01 * w23 + h02 * w25 + h03 * w27;
        float s2o = h10 * w20 + h11 * w22 + h12 * w24 + h13 * w26;
        float s3o = h10 * w21 + h11 * w23 + h12 * w25 + h13 * w27;

        #pragma unroll
        for (int off = 16; off; off >>= 1) {
            s0o += __shfl_down_sync(0xffffffffu, s0o, off);
            s1o += __shfl_down_sync(0xffffffffu, s1o, off);
            s2o += __shfl_down_sync(0xffffffffu, s2o, off);
            s3o += __shfl_down_sync(0xffffffffu, s3o, off);
        }
        if (lane == 0) {
            *(float2*)&out[(size_t)e0 * 2] = make_float2(s0o + bo0, s1o + bo1);
            *(float2*)&out[(size_t)e1 * 2] = make_float2(s2o + bo0, s3o + bo1);
        }
    }
}

// ---------------- launch ----------------
extern "C" void kernel_launch(void* const* d_in, const int* in_sizes, int n_in,
                              void* d_out, int out_size) {
    const float* x    = (const float*)d_in[0];
    const void*  ei   = d_in[1];
    const float* ea   = (const float*)d_in[2];
    const float* e1w  = (const float*)d_in[3];
    const float* e1b  = (const float*)d_in[4];
    const float* m1w1 = (const float*)d_in[5];
    const float* m1b1 = (const float*)d_in[6];
    const float* m1w2 = (const float*)d_in[7];
    const float* m1b2 = (const float*)d_in[8];
    const float* e2w  = (const float*)d_in[9];
    const float* e2b  = (const float*)d_in[10];
    const float* m2w1 = (const float*)d_in[11];
    const float* m2b1 = (const float*)d_in[12];
    const float* m2w2 = (const float*)d_in[13];
    const float* m2b2 = (const float*)d_in[14];
    const float* emw1 = (const float*)d_in[15];
    const float* emb1 = (const float*)d_in[16];
    const float* emw2 = (const float*)d_in[17];
    const float* emb2 = (const float*)d_in[18];
    float* out = (float*)d_out;

    float *aggr1, *h1, *aggr2, *h2;
    cudaGetSymbolAddress((void**)&aggr1, g_aggr1);
    cudaGetSymbolAddress((void**)&h1,    g_h1);
    cudaGetSymbolAddress((void**)&aggr2, g_aggr2);
    cudaGetSymbolAddress((void**)&h2,    g_h2);
    float* gA = aggr1;                                  // reuse aggr1 after conv1
    float* gB = aggr1 + (size_t)N_NODES * HID;

    size_t mlp_smem = (size_t)(128 * 36 + 32 * 132 + 128 * 132) * 4;
    cudaFuncSetAttribute(mlp2_tc, cudaFuncAttributeMaxDynamicSharedMemorySize, (int)mlp_smem);

    int gemm_grid = (N_NODES + 127) / 128;

    convert_idx<<<1024, 256>>>(ei);

    // conv1: aggr init + 3 L2-blocked scatter passes
    copy4<<<4096, 256>>>(x, aggr1, (N_NODES * NODE_IN) / 4);
    edge_msg_pass<0,   false><<<2048, 256>>>(x, ea, e1w, e1b, aggr1);
    edge_msg_pass<128, false><<<2048, 256>>>(x, ea, e1w, e1b, aggr1);
    edge_msg_pass<256, true ><<<2048, 256>>>(x, ea, e1w, e1b, aggr1);
    mlp2_tc<<<gemm_grid, 256, mlp_smem>>>(aggr1, m1w1, m1b1, m1w2, m1b2, h1, N_NODES, NODE_IN);

    // conv2
    copy4<<<2048, 256>>>(h1, aggr2, (N_NODES * HID) / 4);
    edge_msg128<<<2048, 256>>>(h1, ea, e2w, e2b, aggr2);
    mlp2_tc<<<gemm_grid, 256, mlp_smem>>>(aggr2, m2w1, m2b1, m2w2, m2b2, h2, N_NODES, HID);

    // edge MLP (decomposed): gA = h2@Wa, gB = h2@Wb in one launch
    {
        dim3 grid(gemm_grid, 2);
        gemm_tc2<<<grid, 256>>>(h2, emw1, gA, gB, N_NODES);
    }
    edge_out<<<296, 512>>>(gA, gB, ea, emw1, emb1, emw2, emb2, out);
}